// round 12
// baseline (speedup 1.0000x reference)
#include <cuda_runtime.h>
#include <math_constants.h>

#define BB   32
#define TT   2048
#define SINDIM 1024
#define HINDIM 1024
#define KDIM 512
#define VDIM 512
#define NBLK 16            // main-kernel chunks per batch
#define WPB  8             // warps per main block (256 threads)
#define PW   (NBLK*WPB)    // t-stride (128)
#define KSPLIT 4
#define KCH  (KDIM/KSPLIT) // 128

// ---- scratch (device globals; no allocations allowed) ----
__device__ float g_query[BB*KDIM];
__device__ float g_qhp[KSPLIT*BB*HINDIM];
__device__ float g_e[BB*TT];
__device__ float g_pz[BB*NBLK];
__device__ float g_pacc[BB*NBLK*HINDIM];
__device__ float g_ctxh[BB*HINDIM];

__device__ __forceinline__ float warp_sum(float v) {
#pragma unroll
    for (int o = 16; o > 0; o >>= 1) v += __shfl_xor_sync(0xffffffffu, v, o);
    return v;
}

// query[b,k] = Ws[k,:]·dec[b,:] + bs[k].  One warp computes k for 4 batches.
__global__ void k_query(const float* __restrict__ dec, const float* __restrict__ Ws,
                        const float* __restrict__ bs) {
    int gw   = blockIdx.x * 8 + (threadIdx.x >> 5);
    int lane = threadIdx.x & 31;
    int k  = gw % KDIM;
    int b0 = (gw / KDIM) * 4;
    const float4* w4 = (const float4*)(Ws + (size_t)k * SINDIM);
    float4 w[8];
#pragma unroll
    for (int j = 0; j < 8; j++) w[j] = w4[lane + 32*j];
    float bias = bs[k];
#pragma unroll
    for (int bb = 0; bb < 4; bb++) {
        const float4* s4 = (const float4*)(dec + (size_t)(b0+bb) * SINDIM);
        float a = 0.f;
#pragma unroll
        for (int j = 0; j < 8; j++) {
            float4 s = s4[lane + 32*j];
            a += w[j].x*s.x + w[j].y*s.y + w[j].z*s.z + w[j].w*s.w;
        }
        a = warp_sum(a);
        if (lane == 0) g_query[(b0+bb)*KDIM + k] = a + bias;
    }
}

// qh partials: qhp[s][b][h] = sum_{k in chunk s} Wh[k,h]*query[b,k]
__global__ void __launch_bounds__(256) k_qhp(const float* __restrict__ Wh) {
    __shared__ float sq[BB][KCH];          // 16 KB
    const int tid = threadIdx.x;
    const int h   = blockIdx.x * 256 + tid;
    const int k0  = blockIdx.y * KCH;
    for (int i = tid; i < BB*KCH; i += 256)
        sq[i >> 7][i & (KCH-1)] = g_query[(i >> 7)*KDIM + k0 + (i & (KCH-1))];
    __syncthreads();
    float acc[BB];
#pragma unroll
    for (int b = 0; b < BB; b++) acc[b] = 0.f;
#pragma unroll 2
    for (int kk = 0; kk < KCH; kk++) {
        float wh = Wh[(size_t)(k0+kk) * HINDIM + h];
#pragma unroll
        for (int b = 0; b < BB; b++) acc[b] += wh * sq[b][kk];
    }
#pragma unroll
    for (int b = 0; b < BB; b++)
        g_qhp[((size_t)blockIdx.y*BB + b)*HINDIM + h] = acc[b];
}

// MAIN: streaming pass.  R1 shape (256 thr, 1 t/iter, 16 warps/SM) +
// branch-free plain-exp loop (loads of iter i+1 hoistable into reduce chain).
// grid = NBLK*BB (b = blockIdx.x & 31), 256 threads.
__global__ void __launch_bounds__(256) k_main(const float* __restrict__ lo,
                                              const int* __restrict__ lens) {
    __shared__ float s_zs[WPB];
    __shared__ float s_acc[WPB][HINDIM];   // 32 KB

    const int b      = blockIdx.x & (BB-1);
    const int chunk  = blockIdx.x >> 5;
    const int warpId = threadIdx.x >> 5;
    const int lane   = threadIdx.x & 31;
    const int ws     = chunk * WPB + warpId;
    const int len    = (b == 0) ? TT : lens[b];   // ref never masks sample 0

    // q registers = sum of KSPLIT=4 partials (16 KB L2 reads per block)
    float4 q[8];
#pragma unroll
    for (int j = 0; j < 8; j++) q[j] = make_float4(0.f,0.f,0.f,0.f);
#pragma unroll
    for (int s = 0; s < KSPLIT; s++) {
        const float4* p4 = (const float4*)(g_qhp + ((size_t)s*BB + b)*HINDIM);
#pragma unroll
        for (int j = 0; j < 8; j++) {
            float4 v = p4[lane + 32*j];
            q[j].x += v.x; q[j].y += v.y; q[j].z += v.z; q[j].w += v.w;
        }
    }

    float4 acc[8];
#pragma unroll
    for (int j = 0; j < 8; j++) acc[j] = make_float4(0.f,0.f,0.f,0.f);
    float Z = 0.f;

    const float4* lob = (const float4*)(lo + (size_t)b * TT * HINDIM);
    for (int t = ws; t < len; t += PW) {
        const float4* h4 = lob + (size_t)t * (HINDIM/4);
        float4 hv[8];
#pragma unroll
        for (int j = 0; j < 8; j++) hv[j] = h4[lane + 32*j];
        float e = 0.f;
#pragma unroll
        for (int j = 0; j < 8; j++)
            e += hv[j].x*q[j].x + hv[j].y*q[j].y + hv[j].z*q[j].z + hv[j].w*q[j].w;
        e = warp_sum(e);                       // warp-uniform
        if (lane == 0) g_e[b*TT + t] = e;
        float w = __expf(e);                   // no online max: branch-free
        Z += w;
#pragma unroll
        for (int j = 0; j < 8; j++) {
            acc[j].x += w * hv[j].x;
            acc[j].y += w * hv[j].y;
            acc[j].z += w * hv[j].z;
            acc[j].w += w * hv[j].w;
        }
    }

    // ---- in-block merge of 8 warp partials (plain sums) ----
    if (lane == 0) s_zs[warpId] = Z;
    float4* sa = (float4*)(&s_acc[warpId][0]);
#pragma unroll
    for (int j = 0; j < 8; j++) sa[lane + 32*j] = acc[j];
    __syncthreads();
    const int pid = b * NBLK + chunk;
    for (int h = threadIdx.x; h < HINDIM; h += 256) {
        float s = 0.f;
#pragma unroll
        for (int w = 0; w < WPB; w++) s += s_acc[w][h];
        g_pacc[(size_t)pid * HINDIM + h] = s;
    }
    if (threadIdx.x == 0) {
        float zb = 0.f;
#pragma unroll
        for (int w = 0; w < WPB; w++) zb += s_zs[w];
        g_pz[pid] = zb;
    }
}

// cross-block merge (plain sums), grid (BB, 5).
// y = 0..3: ctxh quarter.  y = 4: attn row.
__global__ void __launch_bounds__(256) k_bmerge(const int* __restrict__ lens,
                                                float* __restrict__ out) {
    __shared__ float s_invZ;
    const int b = blockIdx.x, tid = threadIdx.x, slice = blockIdx.y;

    if (tid < 32) {
        float z = (tid < NBLK) ? g_pz[b*NBLK + tid] : 0.f;
        z = warp_sum(z);
        if (tid == 0) s_invZ = 1.f / fmaxf(z, 1e-12f);
    }
    __syncthreads();
    const float invZ = s_invZ;

    if (slice < 4) {
        const int h = slice * 256 + tid;
        float s = 0.f;
#pragma unroll
        for (int j = 0; j < NBLK; j++)
            s += g_pacc[(size_t)(b*NBLK + j)*HINDIM + h];
        g_ctxh[b*HINDIM + h] = s * invZ;
    } else {
        const int len = (b == 0) ? TT : lens[b];
        float* oat = out + BB*VDIM + (size_t)b*TT;
#pragma unroll
        for (int i = 0; i < TT/256; i++) {
            int t = tid + i*256;
            oat[t] = (t < len) ? __expf(g_e[b*TT + t]) * invZ : 0.f;
        }
    }
}

// context[b,v] = Wv[v,:]·ctxh[b,:] + bv[v].  Warp = one v x 4 batches.
__global__ void k_context(const float* __restrict__ Wv, const float* __restrict__ bv,
                          float* __restrict__ out) {
    int gw   = blockIdx.x * 8 + (threadIdx.x >> 5);
    int lane = threadIdx.x & 31;
    int v  = gw % VDIM;
    int b0 = (gw / VDIM) * 4;
    const float4* w4 = (const float4*)(Wv + (size_t)v * HINDIM);
    float4 w[8];
#pragma unroll
    for (int j = 0; j < 8; j++) w[j] = w4[lane + 32*j];
    float bias = bv[v];
#pragma unroll
    for (int bb = 0; bb < 4; bb++) {
        const float4* c4 = (const float4*)(g_ctxh + (size_t)(b0+bb) * HINDIM);
        float a = 0.f;
#pragma unroll
        for (int j = 0; j < 8; j++) {
            float4 c = c4[lane + 32*j];
            a += w[j].x*c.x + w[j].y*c.y + w[j].z*c.z + w[j].w*c.w;
        }
        a = warp_sum(a);
        if (lane == 0) out[(b0+bb)*VDIM + v] = a + bias;
    }
}

extern "C" void kernel_launch(void* const* d_in, const int* in_sizes, int n_in,
                              void* d_out, int out_size) {
    const float* dec = (const float*)d_in[0];
    const float* lo  = (const float*)d_in[1];
    const int*   len = (const int*)  d_in[2];
    const float* Ws  = (const float*)d_in[3];
    const float* bs  = (const float*)d_in[4];
    const float* Wh  = (const float*)d_in[5];
    const float* bh  = (const float*)d_in[6];  // unused: cancels in softmax
    const float* Wv  = (const float*)d_in[7];
    const float* bv  = (const float*)d_in[8];
    float* out = (float*)d_out;
    (void)bh;

    k_query  <<<KDIM * (BB/4) / 8, 256>>>(dec, Ws, bs);       // 512 blocks
    k_qhp    <<<dim3(HINDIM/256, KSPLIT), 256>>>(Wh);         // 16 blocks
    k_main   <<<NBLK * BB, 256>>>(lo, len);                   // 512 blocks
    k_bmerge <<<dim3(BB, 5), 256>>>(len, out);                // 160 blocks
    k_context<<<VDIM * (BB/4) / 8, 256>>>(Wv, bv, out);       // 512 blocks
}

// round 13
// speedup vs baseline: 1.2015x; 1.2015x over previous
#include <cuda_runtime.h>
#include <math_constants.h>

#define BB   32
#define TT   2048
#define SINDIM 1024
#define HINDIM 1024
#define KDIM 512
#define VDIM 512
#define NBLK 16            // main-kernel chunks per batch
#define WPB  8             // warps per main block (256 threads)
#define PW   (NBLK*WPB)    // t-stride (128)

// ---- scratch (device globals; no allocations allowed) ----
__device__ float g_query[BB*KDIM];
__device__ float g_qh[BB*HINDIM];
__device__ float g_e[BB*TT];
__device__ float g_pz[BB*NBLK];
__device__ float g_pacc[BB*NBLK*HINDIM];
__device__ float g_ctxh[BB*HINDIM];

__device__ __forceinline__ float warp_sum(float v) {
#pragma unroll
    for (int o = 16; o > 0; o >>= 1) v += __shfl_xor_sync(0xffffffffu, v, o);
    return v;
}

// query[b,k] = Ws[k,:]·dec[b,:] + bs[k].  One warp computes k for 4 batches.
__global__ void k_query(const float* __restrict__ dec, const float* __restrict__ Ws,
                        const float* __restrict__ bs) {
    int gw   = blockIdx.x * 8 + (threadIdx.x >> 5);
    int lane = threadIdx.x & 31;
    int k  = gw % KDIM;
    int b0 = (gw / KDIM) * 4;
    const float4* w4 = (const float4*)(Ws + (size_t)k * SINDIM);
    float4 w[8];
#pragma unroll
    for (int j = 0; j < 8; j++) w[j] = w4[lane + 32*j];
    float bias = bs[k];
#pragma unroll
    for (int bb = 0; bb < 4; bb++) {
        const float4* s4 = (const float4*)(dec + (size_t)(b0+bb) * SINDIM);
        float a = 0.f;
#pragma unroll
        for (int j = 0; j < 8; j++) {
            float4 s = s4[lane + 32*j];
            a += w[j].x*s.x + w[j].y*s.y + w[j].z*s.z + w[j].w*s.w;
        }
        a = warp_sum(a);
        if (lane == 0) g_query[(b0+bb)*KDIM + k] = a + bias;
    }
}

// qh[b,h] = sum_k Wh[k,h]*query[b,k].  No partials, no merge.
// grid (HINDIM/128, BB/2), 256 threads.  thread: h = tid&127, batch = by*2+(tid>>7).
__global__ void __launch_bounds__(256) k_qh(const float* __restrict__ Wh) {
    __shared__ float sq[2][KDIM];          // 4 KB
    const int tid = threadIdx.x;
    const int h   = blockIdx.x * 128 + (tid & 127);
    const int bb  = tid >> 7;              // 0 or 1
    const int b   = blockIdx.y * 2 + bb;
    for (int i = tid; i < 2*KDIM; i += 256)
        sq[i >> 9][i & (KDIM-1)] = g_query[(blockIdx.y*2 + (i >> 9))*KDIM + (i & (KDIM-1))];
    __syncthreads();
    const float* q = sq[bb];
    float a = 0.f;
#pragma unroll 8
    for (int k = 0; k < KDIM; k++)
        a += Wh[(size_t)k * HINDIM + h] * q[k];
    g_qh[(size_t)b * HINDIM + h] = a;
}

// MAIN: streaming pass, branch-free plain exp, q registers from g_qh (4 KB).
// grid = NBLK*BB (b = blockIdx.x & 31), 256 threads.
__global__ void __launch_bounds__(256) k_main(const float* __restrict__ lo,
                                              const int* __restrict__ lens) {
    __shared__ float s_zs[WPB];
    __shared__ float s_acc[WPB][HINDIM];   // 32 KB

    const int b      = blockIdx.x & (BB-1);
    const int chunk  = blockIdx.x >> 5;
    const int warpId = threadIdx.x >> 5;
    const int lane   = threadIdx.x & 31;
    const int ws     = chunk * WPB + warpId;
    const int len    = (b == 0) ? TT : lens[b];   // ref never masks sample 0

    const float4* qh4 = (const float4*)(g_qh + (size_t)b * HINDIM);
    float4 q[8];
#pragma unroll
    for (int j = 0; j < 8; j++) q[j] = qh4[lane + 32*j];

    float4 acc[8];
#pragma unroll
    for (int j = 0; j < 8; j++) acc[j] = make_float4(0.f,0.f,0.f,0.f);
    float Z = 0.f;

    const float4* lob = (const float4*)(lo + (size_t)b * TT * HINDIM);
    for (int t = ws; t < len; t += PW) {
        const float4* h4 = lob + (size_t)t * (HINDIM/4);
        float4 hv[8];
#pragma unroll
        for (int j = 0; j < 8; j++) hv[j] = h4[lane + 32*j];
        float e = 0.f;
#pragma unroll
        for (int j = 0; j < 8; j++)
            e += hv[j].x*q[j].x + hv[j].y*q[j].y + hv[j].z*q[j].z + hv[j].w*q[j].w;
        e = warp_sum(e);                       // warp-uniform
        if (lane == 0) g_e[b*TT + t] = e;
        float w = __expf(e);                   // no online max: branch-free
        Z += w;
#pragma unroll
        for (int j = 0; j < 8; j++) {
            acc[j].x += w * hv[j].x;
            acc[j].y += w * hv[j].y;
            acc[j].z += w * hv[j].z;
            acc[j].w += w * hv[j].w;
        }
    }

    // ---- in-block merge of 8 warp partials (plain sums) ----
    if (lane == 0) s_zs[warpId] = Z;
    float4* sa = (float4*)(&s_acc[warpId][0]);
#pragma unroll
    for (int j = 0; j < 8; j++) sa[lane + 32*j] = acc[j];
    __syncthreads();
    const int pid = b * NBLK + chunk;
    for (int h = threadIdx.x; h < HINDIM; h += 256) {
        float s = 0.f;
#pragma unroll
        for (int w = 0; w < WPB; w++) s += s_acc[w][h];
        g_pacc[(size_t)pid * HINDIM + h] = s;
    }
    if (threadIdx.x == 0) {
        float zb = 0.f;
#pragma unroll
        for (int w = 0; w < WPB; w++) zb += s_zs[w];
        g_pz[pid] = zb;
    }
}

// cross-block merge (plain sums), grid (BB, 5).
// y = 0..3: ctxh quarter.  y = 4: attn row.
__global__ void __launch_bounds__(256) k_bmerge(const int* __restrict__ lens,
                                                float* __restrict__ out) {
    __shared__ float s_invZ;
    const int b = blockIdx.x, tid = threadIdx.x, slice = blockIdx.y;

    if (tid < 32) {
        float z = (tid < NBLK) ? g_pz[b*NBLK + tid] : 0.f;
        z = warp_sum(z);
        if (tid == 0) s_invZ = 1.f / fmaxf(z, 1e-12f);
    }
    __syncthreads();
    const float invZ = s_invZ;

    if (slice < 4) {
        const int h = slice * 256 + tid;
        float s = 0.f;
#pragma unroll
        for (int j = 0; j < NBLK; j++)
            s += g_pacc[(size_t)(b*NBLK + j)*HINDIM + h];
        g_ctxh[b*HINDIM + h] = s * invZ;
    } else {
        const int len = (b == 0) ? TT : lens[b];
        float* oat = out + BB*VDIM + (size_t)b*TT;
#pragma unroll
        for (int i = 0; i < TT/256; i++) {
            int t = tid + i*256;
            oat[t] = (t < len) ? __expf(g_e[b*TT + t]) * invZ : 0.f;
        }
    }
}

// context[b,v] = Wv[v,:]·ctxh[b,:] + bv[v].  Warp = one v x 4 batches.
__global__ void k_context(const float* __restrict__ Wv, const float* __restrict__ bv,
                          float* __restrict__ out) {
    int gw   = blockIdx.x * 8 + (threadIdx.x >> 5);
    int lane = threadIdx.x & 31;
    int v  = gw % VDIM;
    int b0 = (gw / VDIM) * 4;
    const float4* w4 = (const float4*)(Wv + (size_t)v * HINDIM);
    float4 w[8];
#pragma unroll
    for (int j = 0; j < 8; j++) w[j] = w4[lane + 32*j];
    float bias = bv[v];
#pragma unroll
    for (int bb = 0; bb < 4; bb++) {
        const float4* c4 = (const float4*)(g_ctxh + (size_t)(b0+bb) * HINDIM);
        float a = 0.f;
#pragma unroll
        for (int j = 0; j < 8; j++) {
            float4 c = c4[lane + 32*j];
            a += w[j].x*c.x + w[j].y*c.y + w[j].z*c.z + w[j].w*c.w;
        }
        a = warp_sum(a);
        if (lane == 0) out[(b0+bb)*VDIM + v] = a + bias;
    }
}

extern "C" void kernel_launch(void* const* d_in, const int* in_sizes, int n_in,
                              void* d_out, int out_size) {
    const float* dec = (const float*)d_in[0];
    const float* lo  = (const float*)d_in[1];
    const int*   len = (const int*)  d_in[2];
    const float* Ws  = (const float*)d_in[3];
    const float* bs  = (const float*)d_in[4];
    const float* Wh  = (const float*)d_in[5];
    const float* bh  = (const float*)d_in[6];  // unused: cancels in softmax
    const float* Wv  = (const float*)d_in[7];
    const float* bv  = (const float*)d_in[8];
    float* out = (float*)d_out;
    (void)bh;

    k_query  <<<KDIM * (BB/4) / 8, 256>>>(dec, Ws, bs);       // 512 blocks
    k_qh     <<<dim3(HINDIM/128, BB/2), 256>>>(Wh);           // 128 blocks
    k_main   <<<NBLK * BB, 256>>>(lo, len);                   // 512 blocks
    k_bmerge <<<dim3(BB, 5), 256>>>(len, out);                // 160 blocks
    k_context<<<VDIM * (BB/4) / 8, 256>>>(Wv, bv, out);       // 512 blocks
}